// round 3
// baseline (speedup 1.0000x reference)
#include <cuda_runtime.h>
#include <cstdint>

// Problem constants
#define H      2048   // hidden
#define EI     1024   // expert intermediate
#define NE     8      // num experts
#define NT     2048   // num tokens
#define NVOCAB 32000

// GEMM tiling
#define BM 128
#define BN 128
#define BK 32
#define SA_STRIDE (BK + 4)    // 36 -> conflict-free A frag loads
#define SB_STRIDE (BN + 4)    // 132

// Scratch (no allocations allowed -> __device__ globals)
__device__ float g_gu[(size_t)NT * H];   // gate_up outputs, rows in expert-sorted order
__device__ int   g_perm[NT];             // sorted position -> token (stable order)
__device__ int   g_cnt[NE];
__device__ int   g_off[NE];

// ---------------------------------------------------------------------------
// Routing: stable counting sort, single block of 256 threads.
// Thread t owns tokens [t*8, t*8+8). Local histogram -> smem scan -> stable
// scatter. Fully deterministic.
// ---------------------------------------------------------------------------
#define RT_THREADS 256
#define RT_PER_THR (NT / RT_THREADS)   // 8

__global__ void route_kernel(const int* __restrict__ token_ids) {
    __shared__ int s_hist[RT_THREADS][NE];   // per-thread local counts
    __shared__ int s_total[NE];
    __shared__ int s_exoff[NE];

    const int tid = threadIdx.x;
    int loc[NE];
#pragma unroll
    for (int e = 0; e < NE; e++) loc[e] = 0;

    int eid[RT_PER_THR];
#pragma unroll
    for (int i = 0; i < RT_PER_THR; i++) {
        int id = token_ids[tid * RT_PER_THR + i];
        id = min(max(id, 0), NVOCAB - 1);
        int e = id & (NE - 1);
        eid[i] = e;
        loc[e]++;
    }
#pragma unroll
    for (int e = 0; e < NE; e++) s_hist[tid][e] = loc[e];
    __syncthreads();

    // expert totals (8 threads, each sums one expert's column)
    if (tid < NE) {
        int s = 0;
        for (int t = 0; t < RT_THREADS; t++) s += s_hist[t][tid];
        s_total[tid] = s;
    }
    __syncthreads();
    if (tid == 0) {
        int off = 0;
        for (int e = 0; e < NE; e++) {
            s_exoff[e] = off;
            g_off[e] = off;
            g_cnt[e] = s_total[e];
            off += s_total[e];
        }
    }
    __syncthreads();

    // stable cursor for this thread: expert base + sum of earlier threads' counts
    int cur[NE];
#pragma unroll
    for (int e = 0; e < NE; e++) {
        int c = s_exoff[e];
        for (int t = 0; t < tid; t++) c += s_hist[t][e];
        cur[e] = c;
    }
#pragma unroll
    for (int i = 0; i < RT_PER_THR; i++) {
        int e = eid[i];
        g_perm[cur[e]++] = tid * RT_PER_THR + i;
    }
}

// ---------------------------------------------------------------------------
// tf32 helpers
// ---------------------------------------------------------------------------
__device__ __forceinline__ uint32_t f2tf(float x) {
    uint32_t r;
    asm("cvt.rna.tf32.f32 %0, %1;" : "=r"(r) : "f"(x));   // round-to-nearest: no bias
    return r;
}

__device__ __forceinline__ void mma_tf32(float* d,
                                         uint32_t a0, uint32_t a1, uint32_t a2, uint32_t a3,
                                         uint32_t b0, uint32_t b1) {
    asm volatile(
        "mma.sync.aligned.m16n8k8.row.col.f32.tf32.tf32.f32 "
        "{%0,%1,%2,%3}, {%4,%5,%6,%7}, {%8,%9}, {%0,%1,%2,%3};"
        : "+f"(d[0]), "+f"(d[1]), "+f"(d[2]), "+f"(d[3])
        : "r"(a0), "r"(a1), "r"(a2), "r"(a3), "r"(b0), "r"(b1));
}

__device__ __forceinline__ float silu(float x) {
    return x / (1.0f + __expf(-x));
}

// ---------------------------------------------------------------------------
// GEMM1: gu[pos, 0:2048] = x[perm[pos], :] @ gate_up_proj[e]   (K = 2048)
// grid = (H/BN, NT/BM, NE); blocks with m-tile beyond expert count exit.
// ---------------------------------------------------------------------------
__global__ __launch_bounds__(256)
void gemm1_kernel(const float* __restrict__ x,
                  const float* __restrict__ gate_up) {
    const int e   = blockIdx.z;
    const int cnt = g_cnt[e];
    const int m0  = blockIdx.y * BM;
    if (m0 >= cnt) return;
    const int base = g_off[e];
    const int n0   = blockIdx.x * BN;
    const float* Bp = gate_up + (size_t)e * H * (2 * EI);

    __shared__ uint32_t sA[BM][SA_STRIDE];
    __shared__ uint32_t sB[BK][SB_STRIDE];
    __shared__ int s_tok[BM];

    const int tid = threadIdx.x;
    if (tid < BM) {
        int m = m0 + tid;
        s_tok[tid] = (m < cnt) ? g_perm[base + m] : -1;
    }
    __syncthreads();

    const int warp = tid >> 5, lane = tid & 31;
    const int wm = (warp & 1) * 64;          // 2 warps over M
    const int wn = (warp >> 1) * 32;         // 4 warps over N
    const int grp = lane >> 2, quad = lane & 3;

    float acc[4][4][4];
#pragma unroll
    for (int i = 0; i < 4; i++)
#pragma unroll
        for (int j = 0; j < 4; j++)
#pragma unroll
            for (int r = 0; r < 4; r++) acc[i][j][r] = 0.f;

    for (int k0 = 0; k0 < H; k0 += BK) {
        // A tile: 128 x 32 (gathered rows)
#pragma unroll
        for (int i = 0; i < 4; i++) {
            int f   = tid + i * 256;
            int row = f >> 3;
            int kc  = (f & 7) << 2;
            int tok = s_tok[row];
            float4 v = make_float4(0.f, 0.f, 0.f, 0.f);
            if (tok >= 0)
                v = *reinterpret_cast<const float4*>(x + (size_t)tok * H + k0 + kc);
            sA[row][kc + 0] = f2tf(v.x); sA[row][kc + 1] = f2tf(v.y);
            sA[row][kc + 2] = f2tf(v.z); sA[row][kc + 3] = f2tf(v.w);
        }
        // B tile: 32 x 128
#pragma unroll
        for (int i = 0; i < 4; i++) {
            int f  = tid + i * 256;
            int kr = f >> 5;
            int nc = (f & 31) << 2;
            float4 v = *reinterpret_cast<const float4*>(Bp + (size_t)(k0 + kr) * (2 * EI) + n0 + nc);
            sB[kr][nc + 0] = f2tf(v.x); sB[kr][nc + 1] = f2tf(v.y);
            sB[kr][nc + 2] = f2tf(v.z); sB[kr][nc + 3] = f2tf(v.w);
        }
        __syncthreads();

#pragma unroll
        for (int ks = 0; ks < 4; ks++) {
            const int k = ks * 8;
            uint32_t af[4][4], bf[4][2];
#pragma unroll
            for (int mf = 0; mf < 4; mf++) {
                int mb = wm + mf * 16;
                af[mf][0] = sA[mb + grp][k + quad];
                af[mf][1] = sA[mb + grp + 8][k + quad];
                af[mf][2] = sA[mb + grp][k + quad + 4];
                af[mf][3] = sA[mb + grp + 8][k + quad + 4];
            }
#pragma unroll
            for (int nf = 0; nf < 4; nf++) {
                int nb = wn + nf * 8;
                bf[nf][0] = sB[k + quad][nb + grp];
                bf[nf][1] = sB[k + quad + 4][nb + grp];
            }
#pragma unroll
            for (int mf = 0; mf < 4; mf++)
#pragma unroll
                for (int nf = 0; nf < 4; nf++)
                    mma_tf32(acc[mf][nf], af[mf][0], af[mf][1], af[mf][2], af[mf][3],
                             bf[nf][0], bf[nf][1]);
        }
        __syncthreads();
    }

    // store to scratch g_gu (sorted-row layout)
    const int mrem = cnt - m0;
#pragma unroll
    for (int mf = 0; mf < 4; mf++) {
        int r0 = wm + mf * 16 + grp;
        int r1 = r0 + 8;
#pragma unroll
        for (int nf = 0; nf < 4; nf++) {
            int c = n0 + wn + nf * 8 + quad * 2;
            if (r0 < mrem)
                *reinterpret_cast<float2*>(&g_gu[(size_t)(base + m0 + r0) * H + c]) =
                    make_float2(acc[mf][nf][0], acc[mf][nf][1]);
            if (r1 < mrem)
                *reinterpret_cast<float2*>(&g_gu[(size_t)(base + m0 + r1) * H + c]) =
                    make_float2(acc[mf][nf][2], acc[mf][nf][3]);
        }
    }
}

// ---------------------------------------------------------------------------
// GEMM2: out[perm[pos], :] = (silu(gate)*up)[pos, :] @ down_proj[e]   (K = 1024)
// silu(gate)*up is computed on the fly from g_gu while filling the A tile.
// ---------------------------------------------------------------------------
__global__ __launch_bounds__(256)
void gemm2_kernel(const float* __restrict__ down,
                  float* __restrict__ out) {
    const int e   = blockIdx.z;
    const int cnt = g_cnt[e];
    const int m0  = blockIdx.y * BM;
    if (m0 >= cnt) return;
    const int base = g_off[e];
    const int n0   = blockIdx.x * BN;
    const float* Bp = down + (size_t)e * EI * H;

    __shared__ uint32_t sA[BM][SA_STRIDE];
    __shared__ uint32_t sB[BK][SB_STRIDE];
    __shared__ int s_tok[BM];

    const int tid = threadIdx.x;
    if (tid < BM) {
        int m = m0 + tid;
        s_tok[tid] = (m < cnt) ? g_perm[base + m] : -1;
    }
    __syncthreads();

    const int warp = tid >> 5, lane = tid & 31;
    const int wm = (warp & 1) * 64;
    const int wn = (warp >> 1) * 32;
    const int grp = lane >> 2, quad = lane & 3;

    float acc[4][4][4];
#pragma unroll
    for (int i = 0; i < 4; i++)
#pragma unroll
        for (int j = 0; j < 4; j++)
#pragma unroll
            for (int r = 0; r < 4; r++) acc[i][j][r] = 0.f;

    for (int k0 = 0; k0 < EI; k0 += BK) {
        // A tile: silu(gate)*up computed on the fly
#pragma unroll
        for (int i = 0; i < 4; i++) {
            int f   = tid + i * 256;
            int row = f >> 3;
            int kc  = (f & 7) << 2;
            int tok = s_tok[row];
            float4 r4 = make_float4(0.f, 0.f, 0.f, 0.f);
            if (tok >= 0) {
                size_t rb = (size_t)(base + m0 + row) * H + k0 + kc;
                float4 g = *reinterpret_cast<const float4*>(&g_gu[rb]);
                float4 u = *reinterpret_cast<const float4*>(&g_gu[rb + EI]);
                r4.x = silu(g.x) * u.x; r4.y = silu(g.y) * u.y;
                r4.z = silu(g.z) * u.z; r4.w = silu(g.w) * u.w;
            }
            sA[row][kc + 0] = f2tf(r4.x); sA[row][kc + 1] = f2tf(r4.y);
            sA[row][kc + 2] = f2tf(r4.z); sA[row][kc + 3] = f2tf(r4.w);
        }
        // B tile: 32 x 128 of down_proj[e]
#pragma unroll
        for (int i = 0; i < 4; i++) {
            int f  = tid + i * 256;
            int kr = f >> 5;
            int nc = (f & 31) << 2;
            float4 v = *reinterpret_cast<const float4*>(Bp + (size_t)(k0 + kr) * H + n0 + nc);
            sB[kr][nc + 0] = f2tf(v.x); sB[kr][nc + 1] = f2tf(v.y);
            sB[kr][nc + 2] = f2tf(v.z); sB[kr][nc + 3] = f2tf(v.w);
        }
        __syncthreads();

#pragma unroll
        for (int ks = 0; ks < 4; ks++) {
            const int k = ks * 8;
            uint32_t af[4][4], bf[4][2];
#pragma unroll
            for (int mf = 0; mf < 4; mf++) {
                int mb = wm + mf * 16;
                af[mf][0] = sA[mb + grp][k + quad];
                af[mf][1] = sA[mb + grp + 8][k + quad];
                af[mf][2] = sA[mb + grp][k + quad + 4];
                af[mf][3] = sA[mb + grp + 8][k + quad + 4];
            }
#pragma unroll
            for (int nf = 0; nf < 4; nf++) {
                int nb = wn + nf * 8;
                bf[nf][0] = sB[k + quad][nb + grp];
                bf[nf][1] = sB[k + quad + 4][nb + grp];
            }
#pragma unroll
            for (int mf = 0; mf < 4; mf++)
#pragma unroll
                for (int nf = 0; nf < 4; nf++)
                    mma_tf32(acc[mf][nf], af[mf][0], af[mf][1], af[mf][2], af[mf][3],
                             bf[nf][0], bf[nf][1]);
        }
        __syncthreads();
    }

    // scatter rows back to original token positions
#pragma unroll
    for (int mf = 0; mf < 4; mf++) {
        int r0 = wm + mf * 16 + grp;
        int r1 = r0 + 8;
        int t0 = s_tok[r0];
        int t1 = s_tok[r1];
#pragma unroll
        for (int nf = 0; nf < 4; nf++) {
            int c = n0 + wn + nf * 8 + quad * 2;
            if (t0 >= 0)
                *reinterpret_cast<float2*>(&out[(size_t)t0 * H + c]) =
                    make_float2(acc[mf][nf][0], acc[mf][nf][1]);
            if (t1 >= 0)
                *reinterpret_cast<float2*>(&out[(size_t)t1 * H + c]) =
                    make_float2(acc[mf][nf][2], acc[mf][nf][3]);
        }
    }
}

// ---------------------------------------------------------------------------
// Launch
// ---------------------------------------------------------------------------
extern "C" void kernel_launch(void* const* d_in, const int* in_sizes, int n_in,
                              void* d_out, int out_size) {
    const float* x         = (const float*)d_in[0];
    const int*   token_ids = (const int*)d_in[1];
    const float* gate_up   = (const float*)d_in[2];
    const float* down      = (const float*)d_in[3];
    float*       out       = (float*)d_out;

    route_kernel<<<1, RT_THREADS>>>(token_ids);

    dim3 grid(H / BN, NT / BM, NE);   // fixed worst-case grid; blocks early-exit on counts
    gemm1_kernel<<<grid, 256>>>(x, gate_up);
    gemm2_kernel<<<grid, 256>>>(down, out);
}

// round 4
// speedup vs baseline: 1.8576x; 1.8576x over previous
#include <cuda_runtime.h>
#include <cstdint>

// Problem constants
#define H      2048   // hidden
#define EI     1024   // expert intermediate
#define NE     8      // num experts
#define NT     2048   // num tokens
#define NVOCAB 32000

// GEMM tiling
#define BM 128
#define BN 128
#define BK 32
#define SA_STRIDE (BK + 4)    // 36
#define SB_STRIDE (BN + 4)    // 132

#define SA_ELEMS (BM * SA_STRIDE)            // 4608 floats per stage
#define SB_ELEMS (BK * SB_STRIDE)            // 4224 floats per stage
#define SB_BASE  (2 * SA_ELEMS)              // 9216
#define TOK_BASE (SB_BASE + 2 * SB_ELEMS)    // 17664
#define SMEM_BYTES ((TOK_BASE + BM) * 4)     // 71168 B

// Scratch (no allocations allowed -> __device__ globals)
__device__ float g_gu[(size_t)NT * H];   // gate_up outputs, expert-sorted rows
__device__ float g_h[(size_t)NT * EI];   // silu(gate)*up, expert-sorted rows
__device__ int   g_perm[NT];             // sorted position -> token (stable)
__device__ int   g_cnt[NE];
__device__ int   g_off[NE];

// ---------------------------------------------------------------------------
// Routing: stable counting sort, single block, warp-scan prefix.
// ---------------------------------------------------------------------------
#define RT_THREADS 256
#define RT_PER_THR (NT / RT_THREADS)   // 8

__global__ void route_kernel(const int* __restrict__ token_ids) {
    __shared__ int s_hist[RT_THREADS][NE];
    __shared__ int s_pre[RT_THREADS][NE];
    __shared__ int s_total[NE];
    __shared__ int s_exoff[NE];

    const int tid  = threadIdx.x;
    const int warp = tid >> 5, lane = tid & 31;

    int loc[NE];
#pragma unroll
    for (int e = 0; e < NE; e++) loc[e] = 0;

    int eid[RT_PER_THR];
#pragma unroll
    for (int i = 0; i < RT_PER_THR; i++) {
        int id = token_ids[tid * RT_PER_THR + i];
        id = min(max(id, 0), NVOCAB - 1);
        int e = id & (NE - 1);
        eid[i] = e;
        loc[e]++;
    }
#pragma unroll
    for (int e = 0; e < NE; e++) s_hist[tid][e] = loc[e];
    __syncthreads();

    // warp e computes exclusive prefix over threads for expert e
    if (warp < NE) {
        const int e = warp;
        int run = 0;
        for (int c = 0; c < RT_THREADS; c += 32) {
            int orig = s_hist[c + lane][e];
            int v = orig;
#pragma unroll
            for (int d = 1; d < 32; d <<= 1) {
                int n = __shfl_up_sync(0xFFFFFFFFu, v, d);
                if (lane >= d) v += n;
            }
            s_pre[c + lane][e] = run + v - orig;   // exclusive
            run += __shfl_sync(0xFFFFFFFFu, v, 31);
        }
        if (lane == 31) s_total[e] = run;
    }
    __syncthreads();
    if (tid == 0) {
        int off = 0;
        for (int e = 0; e < NE; e++) {
            s_exoff[e] = off;
            g_off[e] = off;
            g_cnt[e] = s_total[e];
            off += s_total[e];
        }
    }
    __syncthreads();

    int cur[NE];
#pragma unroll
    for (int e = 0; e < NE; e++) cur[e] = s_exoff[e] + s_pre[tid][e];
#pragma unroll
    for (int i = 0; i < RT_PER_THR; i++) {
        int e = eid[i];
        g_perm[cur[e]++] = tid * RT_PER_THR + i;
    }
}

// ---------------------------------------------------------------------------
// helpers
// ---------------------------------------------------------------------------
__device__ __forceinline__ uint32_t f2tf(float x) {
    uint32_t r;
    asm("cvt.rna.tf32.f32 %0, %1;" : "=r"(r) : "f"(x));
    return r;
}

__device__ __forceinline__ void mma_tf32(float* d,
                                         uint32_t a0, uint32_t a1, uint32_t a2, uint32_t a3,
                                         uint32_t b0, uint32_t b1) {
    asm volatile(
        "mma.sync.aligned.m16n8k8.row.col.f32.tf32.tf32.f32 "
        "{%0,%1,%2,%3}, {%4,%5,%6,%7}, {%8,%9}, {%0,%1,%2,%3};"
        : "+f"(d[0]), "+f"(d[1]), "+f"(d[2]), "+f"(d[3])
        : "r"(a0), "r"(a1), "r"(a2), "r"(a3), "r"(b0), "r"(b1));
}

__device__ __forceinline__ float silu(float x) {
    return x / (1.0f + __expf(-x));
}

__device__ __forceinline__ void cp_async16(float* dst_smem, const float* src) {
    uint32_t dst = (uint32_t)__cvta_generic_to_shared(dst_smem);
    asm volatile("cp.async.cg.shared.global [%0], [%1], 16;\n" :: "r"(dst), "l"(src));
}
__device__ __forceinline__ void cp_commit() {
    asm volatile("cp.async.commit_group;\n");
}
__device__ __forceinline__ void cp_wait_all() {
    asm volatile("cp.async.wait_group 0;\n");
}
__device__ __forceinline__ void sts_zero16(float* dst_smem) {
    uint32_t dst = (uint32_t)__cvta_generic_to_shared(dst_smem);
    asm volatile("st.shared.v4.b32 [%0], {%1,%1,%1,%1};\n" :: "r"(dst), "r"(0));
}

// ---------------------------------------------------------------------------
// GEMM1: g_gu[pos, :] = x[perm[pos], :] @ gate_up_proj[e]   (K = H)
// 2-stage cp.async pipeline, raw f32 in smem, cvt at fragment read.
// ---------------------------------------------------------------------------
__global__ __launch_bounds__(256, 2)
void gemm1_kernel(const float* __restrict__ x,
                  const float* __restrict__ gate_up) {
    const int e   = blockIdx.z;
    const int cnt = g_cnt[e];
    const int m0  = blockIdx.y * BM;
    if (m0 >= cnt) return;
    const int base = g_off[e];
    const int n0   = blockIdx.x * BN;
    const float* Bp = gate_up + (size_t)e * H * (2 * EI);

    extern __shared__ float sm[];
    int* s_tok = (int*)(sm + TOK_BASE);

    const int tid = threadIdx.x;
    if (tid < BM) {
        int m = m0 + tid;
        s_tok[tid] = (m < cnt) ? g_perm[base + m] : -1;
    }
    __syncthreads();

    const int warp = tid >> 5, lane = tid & 31;
    const int wm = (warp & 1) * 64;
    const int wn = (warp >> 1) * 32;
    const int grp = lane >> 2, quad = lane & 3;

    // per-thread staging coordinates
    const int a_row = tid >> 3;              // +32 per i
    const int a_kc  = (tid & 7) << 2;
    const int b_kr  = tid >> 5;              // +8 per i
    const int b_nc  = (tid & 31) << 2;

    float acc[4][4][4];
#pragma unroll
    for (int i = 0; i < 4; i++)
#pragma unroll
        for (int j = 0; j < 4; j++)
#pragma unroll
            for (int r = 0; r < 4; r++) acc[i][j][r] = 0.f;

#define LOAD_STAGE1(KT0, BUF)                                                   \
    {                                                                           \
        float* sa = sm + (BUF) * SA_ELEMS;                                      \
        float* sb = sm + SB_BASE + (BUF) * SB_ELEMS;                            \
        _Pragma("unroll")                                                       \
        for (int i = 0; i < 4; i++) {                                           \
            int row = a_row + i * 32;                                           \
            int tok = s_tok[row];                                               \
            float* d = sa + row * SA_STRIDE + a_kc;                             \
            if (tok >= 0)                                                       \
                cp_async16(d, x + (size_t)tok * H + (KT0) + a_kc);              \
            else                                                                \
                sts_zero16(d);                                                  \
        }                                                                       \
        _Pragma("unroll")                                                       \
        for (int i = 0; i < 4; i++) {                                           \
            int kr = b_kr + i * 8;                                              \
            cp_async16(sb + kr * SB_STRIDE + b_nc,                              \
                       Bp + (size_t)((KT0) + kr) * (2 * EI) + n0 + b_nc);       \
        }                                                                       \
        cp_commit();                                                            \
    }

    LOAD_STAGE1(0, 0);

    const int KT = H / BK;
    for (int kt = 0; kt < KT; kt++) {
        cp_wait_all();
        __syncthreads();
        if (kt + 1 < KT) LOAD_STAGE1((kt + 1) * BK, (kt + 1) & 1);

        const int buf = kt & 1;
        const float* sa = sm + buf * SA_ELEMS;
        const float* sb = sm + SB_BASE + buf * SB_ELEMS;

#pragma unroll
        for (int ks = 0; ks < 4; ks++) {
            const int k = ks * 8;
            uint32_t af[4][4], bf[4][2];
#pragma unroll
            for (int mf = 0; mf < 4; mf++) {
                int mb = wm + mf * 16;
                af[mf][0] = f2tf(sa[(mb + grp) * SA_STRIDE + k + quad]);
                af[mf][1] = f2tf(sa[(mb + grp + 8) * SA_STRIDE + k + quad]);
                af[mf][2] = f2tf(sa[(mb + grp) * SA_STRIDE + k + quad + 4]);
                af[mf][3] = f2tf(sa[(mb + grp + 8) * SA_STRIDE + k + quad + 4]);
            }
#pragma unroll
            for (int nf = 0; nf < 4; nf++) {
                int nb = wn + nf * 8;
                bf[nf][0] = f2tf(sb[(k + quad) * SB_STRIDE + nb + grp]);
                bf[nf][1] = f2tf(sb[(k + quad + 4) * SB_STRIDE + nb + grp]);
            }
#pragma unroll
            for (int mf = 0; mf < 4; mf++)
#pragma unroll
                for (int nf = 0; nf < 4; nf++)
                    mma_tf32(acc[mf][nf], af[mf][0], af[mf][1], af[mf][2], af[mf][3],
                             bf[nf][0], bf[nf][1]);
        }
        __syncthreads();
    }

    const int mrem = cnt - m0;
#pragma unroll
    for (int mf = 0; mf < 4; mf++) {
        int r0 = wm + mf * 16 + grp;
        int r1 = r0 + 8;
#pragma unroll
        for (int nf = 0; nf < 4; nf++) {
            int c = n0 + wn + nf * 8 + quad * 2;
            if (r0 < mrem)
                *reinterpret_cast<float2*>(&g_gu[(size_t)(base + m0 + r0) * H + c]) =
                    make_float2(acc[mf][nf][0], acc[mf][nf][1]);
            if (r1 < mrem)
                *reinterpret_cast<float2*>(&g_gu[(size_t)(base + m0 + r1) * H + c]) =
                    make_float2(acc[mf][nf][2], acc[mf][nf][3]);
        }
    }
}

// ---------------------------------------------------------------------------
// Activation: g_h[row, 0:EI] = silu(g_gu[row, 0:EI]) * g_gu[row, EI:2EI]
// ---------------------------------------------------------------------------
__global__ __launch_bounds__(256)
void act_kernel() {
    int idx = blockIdx.x * blockDim.x + threadIdx.x;   // over NT*EI/4
    int row = idx / (EI / 4);
    int c   = (idx % (EI / 4)) * 4;
    float4 g = *reinterpret_cast<const float4*>(&g_gu[(size_t)row * H + c]);
    float4 u = *reinterpret_cast<const float4*>(&g_gu[(size_t)row * H + c + EI]);
    float4 h;
    h.x = silu(g.x) * u.x; h.y = silu(g.y) * u.y;
    h.z = silu(g.z) * u.z; h.w = silu(g.w) * u.w;
    *reinterpret_cast<float4*>(&g_h[(size_t)row * EI + c]) = h;
}

// ---------------------------------------------------------------------------
// GEMM2: out[perm[pos], :] = g_h[pos, :] @ down_proj[e]   (K = EI)
// ---------------------------------------------------------------------------
__global__ __launch_bounds__(256, 2)
void gemm2_kernel(const float* __restrict__ down,
                  float* __restrict__ out) {
    const int e   = blockIdx.z;
    const int cnt = g_cnt[e];
    const int m0  = blockIdx.y * BM;
    if (m0 >= cnt) return;
    const int base = g_off[e];
    const int n0   = blockIdx.x * BN;
    const float* Bp = down + (size_t)e * EI * H;

    extern __shared__ float sm[];
    int* s_tok = (int*)(sm + TOK_BASE);

    const int tid = threadIdx.x;
    if (tid < BM) {
        int m = m0 + tid;
        s_tok[tid] = (m < cnt) ? g_perm[base + m] : -1;
    }
    __syncthreads();

    const int warp = tid >> 5, lane = tid & 31;
    const int wm = (warp & 1) * 64;
    const int wn = (warp >> 1) * 32;
    const int grp = lane >> 2, quad = lane & 3;

    const int a_row = tid >> 3;
    const int a_kc  = (tid & 7) << 2;
    const int b_kr  = tid >> 5;
    const int b_nc  = (tid & 31) << 2;

    float acc[4][4][4];
#pragma unroll
    for (int i = 0; i < 4; i++)
#pragma unroll
        for (int j = 0; j < 4; j++)
#pragma unroll
            for (int r = 0; r < 4; r++) acc[i][j][r] = 0.f;

#define LOAD_STAGE2(KT0, BUF)                                                   \
    {                                                                           \
        float* sa = sm + (BUF) * SA_ELEMS;                                      \
        float* sb = sm + SB_BASE + (BUF) * SB_ELEMS;                            \
        _Pragma("unroll")                                                       \
        for (int i = 0; i < 4; i++) {                                           \
            int row = a_row + i * 32;                                           \
            float* d = sa + row * SA_STRIDE + a_kc;                             \
            if (s_tok[row] >= 0)                                                \
                cp_async16(d, g_h + (size_t)(base + m0 + row) * EI + (KT0) + a_kc); \
            else                                                                \
                sts_zero16(d);                                                  \
        }                                                                       \
        _Pragma("unroll")                                                       \
        for (int i = 0; i < 4; i++) {                                           \
            int kr = b_kr + i * 8;                                              \
            cp_async16(sb + kr * SB_STRIDE + b_nc,                              \
                       Bp + (size_t)((KT0) + kr) * H + n0 + b_nc);              \
        }                                                                       \
        cp_commit();                                                            \
    }

    LOAD_STAGE2(0, 0);

    const int KT = EI / BK;
    for (int kt = 0; kt < KT; kt++) {
        cp_wait_all();
        __syncthreads();
        if (kt + 1 < KT) LOAD_STAGE2((kt + 1) * BK, (kt + 1) & 1);

        const int buf = kt & 1;
        const float* sa = sm + buf * SA_ELEMS;
        const float* sb = sm + SB_BASE + buf * SB_ELEMS;

#pragma unroll
        for (int ks = 0; ks < 4; ks++) {
            const int k = ks * 8;
            uint32_t af[4][4], bf[4][2];
#pragma unroll
            for (int mf = 0; mf < 4; mf++) {
                int mb = wm + mf * 16;
                af[mf][0] = f2tf(sa[(mb + grp) * SA_STRIDE + k + quad]);
                af[mf][1] = f2tf(sa[(mb + grp + 8) * SA_STRIDE + k + quad]);
                af[mf][2] = f2tf(sa[(mb + grp) * SA_STRIDE + k + quad + 4]);
                af[mf][3] = f2tf(sa[(mb + grp + 8) * SA_STRIDE + k + quad + 4]);
            }
#pragma unroll
            for (int nf = 0; nf < 4; nf++) {
                int nb = wn + nf * 8;
                bf[nf][0] = f2tf(sb[(k + quad) * SB_STRIDE + nb + grp]);
                bf[nf][1] = f2tf(sb[(k + quad + 4) * SB_STRIDE + nb + grp]);
            }
#pragma unroll
            for (int mf = 0; mf < 4; mf++)
#pragma unroll
                for (int nf = 0; nf < 4; nf++)
                    mma_tf32(acc[mf][nf], af[mf][0], af[mf][1], af[mf][2], af[mf][3],
                             bf[nf][0], bf[nf][1]);
        }
        __syncthreads();
    }

    // scatter rows back to original token positions
#pragma unroll
    for (int mf = 0; mf < 4; mf++) {
        int r0 = wm + mf * 16 + grp;
        int r1 = r0 + 8;
        int t0 = s_tok[r0];
        int t1 = s_tok[r1];
#pragma unroll
        for (int nf = 0; nf < 4; nf++) {
            int c = n0 + wn + nf * 8 + quad * 2;
            if (t0 >= 0)
                *reinterpret_cast<float2*>(&out[(size_t)t0 * H + c]) =
                    make_float2(acc[mf][nf][0], acc[mf][nf][1]);
            if (t1 >= 0)
                *reinterpret_cast<float2*>(&out[(size_t)t1 * H + c]) =
                    make_float2(acc[mf][nf][2], acc[mf][nf][3]);
        }
    }
}

// ---------------------------------------------------------------------------
// Launch
// ---------------------------------------------------------------------------
extern "C" void kernel_launch(void* const* d_in, const int* in_sizes, int n_in,
                              void* d_out, int out_size) {
    const float* x         = (const float*)d_in[0];
    const int*   token_ids = (const int*)d_in[1];
    const float* gate_up   = (const float*)d_in[2];
    const float* down      = (const float*)d_in[3];
    float*       out       = (float*)d_out;

    cudaFuncSetAttribute(gemm1_kernel, cudaFuncAttributeMaxDynamicSharedMemorySize, SMEM_BYTES);
    cudaFuncSetAttribute(gemm2_kernel, cudaFuncAttributeMaxDynamicSharedMemorySize, SMEM_BYTES);

    route_kernel<<<1, RT_THREADS>>>(token_ids);

    dim3 grid(H / BN, NT / BM, NE);   // fixed worst-case grid; blocks early-exit on counts
    gemm1_kernel<<<grid, 256, SMEM_BYTES>>>(x, gate_up);
    act_kernel<<<(NT * EI / 4) / 256, 256>>>();
    gemm2_kernel<<<grid, 256, SMEM_BYTES>>>(down, out);
}

// round 5
// speedup vs baseline: 1.9526x; 1.0511x over previous
#include <cuda_runtime.h>
#include <cstdint>

// Problem constants
#define H      2048   // hidden
#define EI     1024   // expert intermediate
#define NE     8      // num experts
#define NT     2048   // num tokens
#define NVOCAB 32000

// GEMM tiling
#define BM 128
#define BN 128
#define BK 32
#define SA_STRIDE (BK + 4)    // 36
#define SB_STRIDE (BN + 4)    // 132

#define NSTAGE 3
#define SA_ELEMS (BM * SA_STRIDE)                 // 4608 floats/stage
#define SB_ELEMS (BK * SB_STRIDE)                 // 4224 floats/stage
#define SB_BASE  (NSTAGE * SA_ELEMS)              // 13824
#define TOK_BASE (SB_BASE + NSTAGE * SB_ELEMS)    // 26496
#define SMEM_BYTES ((TOK_BASE + BM) * 4)          // 106496 B -> 2 CTAs/SM

// Scratch (no allocations allowed -> __device__ globals)
__device__ float g_xr[(size_t)NT * H];   // x pre-rounded to tf32
__device__ float g_gu[(size_t)NT * H];   // gate_up outputs, expert-sorted rows
__device__ float g_h[(size_t)NT * EI];   // silu(gate)*up, tf32-rounded, sorted rows
__device__ int   g_perm[NT];
__device__ int   g_cnt[NE];
__device__ int   g_off[NE];

// ---------------------------------------------------------------------------
// Routing: stable counting sort, single block, warp-scan prefix.
// ---------------------------------------------------------------------------
#define RT_THREADS 256
#define RT_PER_THR (NT / RT_THREADS)   // 8

__global__ void route_kernel(const int* __restrict__ token_ids) {
    __shared__ int s_hist[RT_THREADS][NE];
    __shared__ int s_pre[RT_THREADS][NE];
    __shared__ int s_total[NE];
    __shared__ int s_exoff[NE];

    const int tid  = threadIdx.x;
    const int warp = tid >> 5, lane = tid & 31;

    int loc[NE];
#pragma unroll
    for (int e = 0; e < NE; e++) loc[e] = 0;

    int eid[RT_PER_THR];
#pragma unroll
    for (int i = 0; i < RT_PER_THR; i++) {
        int id = token_ids[tid * RT_PER_THR + i];
        id = min(max(id, 0), NVOCAB - 1);
        int e = id & (NE - 1);
        eid[i] = e;
        loc[e]++;
    }
#pragma unroll
    for (int e = 0; e < NE; e++) s_hist[tid][e] = loc[e];
    __syncthreads();

    if (warp < NE) {
        const int e = warp;
        int run = 0;
        for (int c = 0; c < RT_THREADS; c += 32) {
            int orig = s_hist[c + lane][e];
            int v = orig;
#pragma unroll
            for (int d = 1; d < 32; d <<= 1) {
                int n = __shfl_up_sync(0xFFFFFFFFu, v, d);
                if (lane >= d) v += n;
            }
            s_pre[c + lane][e] = run + v - orig;
            run += __shfl_sync(0xFFFFFFFFu, v, 31);
        }
        if (lane == 31) s_total[e] = run;
    }
    __syncthreads();
    if (tid == 0) {
        int off = 0;
        for (int e = 0; e < NE; e++) {
            s_exoff[e] = off;
            g_off[e] = off;
            g_cnt[e] = s_total[e];
            off += s_total[e];
        }
    }
    __syncthreads();

    int cur[NE];
#pragma unroll
    for (int e = 0; e < NE; e++) cur[e] = s_exoff[e] + s_pre[tid][e];
#pragma unroll
    for (int i = 0; i < RT_PER_THR; i++) {
        int e = eid[i];
        g_perm[cur[e]++] = tid * RT_PER_THR + i;
    }
}

// ---------------------------------------------------------------------------
// helpers
// ---------------------------------------------------------------------------
__device__ __forceinline__ uint32_t f2tf(float x) {
    uint32_t r;
    asm("cvt.rna.tf32.f32 %0, %1;" : "=r"(r) : "f"(x));
    return r;
}

__device__ __forceinline__ void mma_tf32(float* d,
                                         uint32_t a0, uint32_t a1, uint32_t a2, uint32_t a3,
                                         uint32_t b0, uint32_t b1) {
    asm volatile(
        "mma.sync.aligned.m16n8k8.row.col.f32.tf32.tf32.f32 "
        "{%0,%1,%2,%3}, {%4,%5,%6,%7}, {%8,%9}, {%0,%1,%2,%3};"
        : "+f"(d[0]), "+f"(d[1]), "+f"(d[2]), "+f"(d[3])
        : "r"(a0), "r"(a1), "r"(a2), "r"(a3), "r"(b0), "r"(b1));
}

__device__ __forceinline__ float silu(float x) {
    return x / (1.0f + __expf(-x));
}

__device__ __forceinline__ void cp_async16(float* dst_smem, const float* src) {
    uint32_t dst = (uint32_t)__cvta_generic_to_shared(dst_smem);
    asm volatile("cp.async.cg.shared.global [%0], [%1], 16;\n" :: "r"(dst), "l"(src));
}
__device__ __forceinline__ void cp_commit() {
    asm volatile("cp.async.commit_group;\n");
}
__device__ __forceinline__ void cp_wait_1() {
    asm volatile("cp.async.wait_group 1;\n");
}

// ---------------------------------------------------------------------------
// Pre-round x to tf32 (rna) so GEMM1 A-tiles need no cvt in the mainloop.
// ---------------------------------------------------------------------------
__global__ __launch_bounds__(256)
void round_x_kernel(const float* __restrict__ x) {
    int idx = (blockIdx.x * blockDim.x + threadIdx.x) * 4;
    float4 v = *reinterpret_cast<const float4*>(x + idx);
    v.x = __uint_as_float(f2tf(v.x));
    v.y = __uint_as_float(f2tf(v.y));
    v.z = __uint_as_float(f2tf(v.z));
    v.w = __uint_as_float(f2tf(v.w));
    *reinterpret_cast<float4*>(&g_xr[idx]) = v;
}

// ---------------------------------------------------------------------------
// GEMM1: g_gu[pos, :] = xr[perm[pos], :] @ gate_up_proj[e]   (K = H)
// 3-stage cp.async pipeline, one barrier per K-iter, A pre-rounded (no cvt).
// ---------------------------------------------------------------------------
__global__ __launch_bounds__(256, 2)
void gemm1_kernel(const float* __restrict__ gate_up) {
    const int e   = blockIdx.z;
    const int cnt = g_cnt[e];
    const int m0  = blockIdx.y * BM;
    if (m0 >= cnt) return;
    const int base = g_off[e];
    const int n0   = blockIdx.x * BN;
    const float* Bp = gate_up + (size_t)e * H * (2 * EI);

    extern __shared__ float sm[];
    int* s_tok = (int*)(sm + TOK_BASE);

    const int tid = threadIdx.x;
    if (tid < BM) {
        int m = min(base + m0 + tid, NT - 1);   // clamped; rows >= cnt never stored
        s_tok[tid] = g_perm[m];
    }
    __syncthreads();

    const int warp = tid >> 5, lane = tid & 31;
    const int wm = (warp & 1) * 64;
    const int wn = (warp >> 1) * 32;
    const int grp = lane >> 2, quad = lane & 3;

    const int a_row = tid >> 3;
    const int a_kc  = (tid & 7) << 2;
    const int b_kr  = tid >> 5;
    const int b_nc  = (tid & 31) << 2;

    float acc[4][4][4];
#pragma unroll
    for (int i = 0; i < 4; i++)
#pragma unroll
        for (int j = 0; j < 4; j++)
#pragma unroll
            for (int r = 0; r < 4; r++) acc[i][j][r] = 0.f;

#define LOAD_STAGE1(KT0, BUF)                                                   \
    {                                                                           \
        float* sa = sm + (BUF) * SA_ELEMS;                                      \
        float* sb = sm + SB_BASE + (BUF) * SB_ELEMS;                            \
        _Pragma("unroll")                                                       \
        for (int i = 0; i < 4; i++) {                                           \
            int row = a_row + i * 32;                                           \
            cp_async16(sa + row * SA_STRIDE + a_kc,                             \
                       g_xr + (size_t)s_tok[row] * H + (KT0) + a_kc);           \
        }                                                                       \
        _Pragma("unroll")                                                       \
        for (int i = 0; i < 4; i++) {                                           \
            int kr = b_kr + i * 8;                                              \
            cp_async16(sb + kr * SB_STRIDE + b_nc,                              \
                       Bp + (size_t)((KT0) + kr) * (2 * EI) + n0 + b_nc);       \
        }                                                                       \
        cp_commit();                                                            \
    }

    LOAD_STAGE1(0, 0);
    LOAD_STAGE1(BK, 1);

    const int KT = H / BK;
    for (int kt = 0; kt < KT; kt++) {
        cp_wait_1();
        __syncthreads();
        if (kt + 2 < KT) LOAD_STAGE1((kt + 2) * BK, (kt + 2) % NSTAGE);

        const int buf = kt % NSTAGE;
        const float* sa = sm + buf * SA_ELEMS;
        const float* sb = sm + SB_BASE + buf * SB_ELEMS;

#pragma unroll
        for (int ks = 0; ks < 4; ks++) {
            const int k = ks * 8;
            uint32_t af[4][4], bf[4][2];
#pragma unroll
            for (int mf = 0; mf < 4; mf++) {
                int mb = wm + mf * 16;
                af[mf][0] = __float_as_uint(sa[(mb + grp) * SA_STRIDE + k + quad]);
                af[mf][1] = __float_as_uint(sa[(mb + grp + 8) * SA_STRIDE + k + quad]);
                af[mf][2] = __float_as_uint(sa[(mb + grp) * SA_STRIDE + k + quad + 4]);
                af[mf][3] = __float_as_uint(sa[(mb + grp + 8) * SA_STRIDE + k + quad + 4]);
            }
#pragma unroll
            for (int nf = 0; nf < 4; nf++) {
                int nb = wn + nf * 8;
                bf[nf][0] = f2tf(sb[(k + quad) * SB_STRIDE + nb + grp]);
                bf[nf][1] = f2tf(sb[(k + quad + 4) * SB_STRIDE + nb + grp]);
            }
#pragma unroll
            for (int mf = 0; mf < 4; mf++)
#pragma unroll
                for (int nf = 0; nf < 4; nf++)
                    mma_tf32(acc[mf][nf], af[mf][0], af[mf][1], af[mf][2], af[mf][3],
                             bf[nf][0], bf[nf][1]);
        }
    }

    const int mrem = cnt - m0;
#pragma unroll
    for (int mf = 0; mf < 4; mf++) {
        int r0 = wm + mf * 16 + grp;
        int r1 = r0 + 8;
#pragma unroll
        for (int nf = 0; nf < 4; nf++) {
            int c = n0 + wn + nf * 8 + quad * 2;
            if (r0 < mrem)
                *reinterpret_cast<float2*>(&g_gu[(size_t)(base + m0 + r0) * H + c]) =
                    make_float2(acc[mf][nf][0], acc[mf][nf][1]);
            if (r1 < mrem)
                *reinterpret_cast<float2*>(&g_gu[(size_t)(base + m0 + r1) * H + c]) =
                    make_float2(acc[mf][nf][2], acc[mf][nf][3]);
        }
    }
}

// ---------------------------------------------------------------------------
// Activation: g_h = tf32_round(silu(gate) * up)
// ---------------------------------------------------------------------------
__global__ __launch_bounds__(256)
void act_kernel() {
    int idx = blockIdx.x * blockDim.x + threadIdx.x;
    int row = idx / (EI / 4);
    int c   = (idx % (EI / 4)) * 4;
    float4 g = *reinterpret_cast<const float4*>(&g_gu[(size_t)row * H + c]);
    float4 u = *reinterpret_cast<const float4*>(&g_gu[(size_t)row * H + c + EI]);
    float4 h;
    h.x = __uint_as_float(f2tf(silu(g.x) * u.x));
    h.y = __uint_as_float(f2tf(silu(g.y) * u.y));
    h.z = __uint_as_float(f2tf(silu(g.z) * u.z));
    h.w = __uint_as_float(f2tf(silu(g.w) * u.w));
    *reinterpret_cast<float4*>(&g_h[(size_t)row * EI + c]) = h;
}

// ---------------------------------------------------------------------------
// GEMM2: out[perm[pos], :] = g_h[pos, :] @ down_proj[e]   (K = EI)
// ---------------------------------------------------------------------------
__global__ __launch_bounds__(256, 2)
void gemm2_kernel(const float* __restrict__ down,
                  float* __restrict__ out) {
    const int e   = blockIdx.z;
    const int cnt = g_cnt[e];
    const int m0  = blockIdx.y * BM;
    if (m0 >= cnt) return;
    const int base = g_off[e];
    const int n0   = blockIdx.x * BN;
    const float* Bp = down + (size_t)e * EI * H;

    extern __shared__ float sm[];
    int* s_tok = (int*)(sm + TOK_BASE);

    const int tid = threadIdx.x;
    if (tid < BM) {
        int m = min(base + m0 + tid, NT - 1);
        s_tok[tid] = g_perm[m];
    }
    __syncthreads();

    const int warp = tid >> 5, lane = tid & 31;
    const int wm = (warp & 1) * 64;
    const int wn = (warp >> 1) * 32;
    const int grp = lane >> 2, quad = lane & 3;

    const int a_row = tid >> 3;
    const int a_kc  = (tid & 7) << 2;
    const int b_kr  = tid >> 5;
    const int b_nc  = (tid & 31) << 2;

    float acc[4][4][4];
#pragma unroll
    for (int i = 0; i < 4; i++)
#pragma unroll
        for (int j = 0; j < 4; j++)
#pragma unroll
            for (int r = 0; r < 4; r++) acc[i][j][r] = 0.f;

#define LOAD_STAGE2(KT0, BUF)                                                   \
    {                                                                           \
        float* sa = sm + (BUF) * SA_ELEMS;                                      \
        float* sb = sm + SB_BASE + (BUF) * SB_ELEMS;                            \
        _Pragma("unroll")                                                       \
        for (int i = 0; i < 4; i++) {                                           \
            int row = a_row + i * 32;                                           \
            int rg  = min(base + m0 + row, NT - 1);                             \
            cp_async16(sa + row * SA_STRIDE + a_kc,                             \
                       g_h + (size_t)rg * EI + (KT0) + a_kc);                   \
        }                                                                       \
        _Pragma("unroll")                                                       \
        for (int i = 0; i < 4; i++) {                                           \
            int kr = b_kr + i * 8;                                              \
            cp_async16(sb + kr * SB_STRIDE + b_nc,                              \
                       Bp + (size_t)((KT0) + kr) * H + n0 + b_nc);              \
        }                                                                       \
        cp_commit();                                                            \
    }

    LOAD_STAGE2(0, 0);
    LOAD_STAGE2(BK, 1);

    const int KT = EI / BK;
    for (int kt = 0; kt < KT; kt++) {
        cp_wait_1();
        __syncthreads();
        if (kt + 2 < KT) LOAD_STAGE2((kt + 2) * BK, (kt + 2) % NSTAGE);

        const int buf = kt % NSTAGE;
        const float* sa = sm + buf * SA_ELEMS;
        const float* sb = sm + SB_BASE + buf * SB_ELEMS;

#pragma unroll
        for (int ks = 0; ks < 4; ks++) {
            const int k = ks * 8;
            uint32_t af[4][4], bf[4][2];
#pragma unroll
            for (int mf = 0; mf < 4; mf++) {
                int mb = wm + mf * 16;
                af[mf][0] = __float_as_uint(sa[(mb + grp) * SA_STRIDE + k + quad]);
                af[mf][1] = __float_as_uint(sa[(mb + grp + 8) * SA_STRIDE + k + quad]);
                af[mf][2] = __float_as_uint(sa[(mb + grp) * SA_STRIDE + k + quad + 4]);
                af[mf][3] = __float_as_uint(sa[(mb + grp + 8) * SA_STRIDE + k + quad + 4]);
            }
#pragma unroll
            for (int nf = 0; nf < 4; nf++) {
                int nb = wn + nf * 8;
                bf[nf][0] = f2tf(sb[(k + quad) * SB_STRIDE + nb + grp]);
                bf[nf][1] = f2tf(sb[(k + quad + 4) * SB_STRIDE + nb + grp]);
            }
#pragma unroll
            for (int mf = 0; mf < 4; mf++)
#pragma unroll
                for (int nf = 0; nf < 4; nf++)
                    mma_tf32(acc[mf][nf], af[mf][0], af[mf][1], af[mf][2], af[mf][3],
                             bf[nf][0], bf[nf][1]);
        }
    }

    const int mrem = cnt - m0;
#pragma unroll
    for (int mf = 0; mf < 4; mf++) {
        int r0 = wm + mf * 16 + grp;
        int r1 = r0 + 8;
        int t0 = s_tok[r0];
        int t1 = s_tok[r1];
#pragma unroll
        for (int nf = 0; nf < 4; nf++) {
            int c = n0 + wn + nf * 8 + quad * 2;
            if (r0 < mrem)
                *reinterpret_cast<float2*>(&out[(size_t)t0 * H + c]) =
                    make_float2(acc[mf][nf][0], acc[mf][nf][1]);
            if (r1 < mrem)
                *reinterpret_cast<float2*>(&out[(size_t)t1 * H + c]) =
                    make_float2(acc[mf][nf][2], acc[mf][nf][3]);
        }
    }
}

// ---------------------------------------------------------------------------
// Launch
// ---------------------------------------------------------------------------
extern "C" void kernel_launch(void* const* d_in, const int* in_sizes, int n_in,
                              void* d_out, int out_size) {
    const float* x         = (const float*)d_in[0];
    const int*   token_ids = (const int*)d_in[1];
    const float* gate_up   = (const float*)d_in[2];
    const float* down      = (const float*)d_in[3];
    float*       out       = (float*)d_out;

    cudaFuncSetAttribute(gemm1_kernel, cudaFuncAttributeMaxDynamicSharedMemorySize, SMEM_BYTES);
    cudaFuncSetAttribute(gemm2_kernel, cudaFuncAttributeMaxDynamicSharedMemorySize, SMEM_BYTES);

    route_kernel<<<1, RT_THREADS>>>(token_ids);
    round_x_kernel<<<(NT * H / 4) / 256, 256>>>(x);

    dim3 grid(H / BN, NT / BM, NE);   // fixed worst-case grid; blocks early-exit on counts
    gemm1_kernel<<<grid, 256, SMEM_BYTES>>>(gate_up);
    act_kernel<<<(NT * EI / 4) / 256, 256>>>();
    gemm2_kernel<<<grid, 256, SMEM_BYTES>>>(down, out);
}

// round 8
// speedup vs baseline: 2.5199x; 1.2905x over previous
#include <cuda_runtime.h>
#include <cuda_fp16.h>
#include <cstdint>

// Problem constants
#define H      2048
#define EI     1024
#define NE     8
#define NT     2048
#define NVOCAB 32000

// GEMM tiling: 128 x 64 tile, BK = 32 k-halves per stage, 8 warps (2M x 4N)
#define BM 128
#define BN 64
#define BK 32

// smem layout per stage:
//   A: fp16 [128][32], row stride 40 halves = 80 B
//   B: f32  [32][64],  row stride 68 floats = 272 B (conflict-free frags)
#define AROWB 80
#define BROWB 272
#define A_BYTES (128 * AROWB)            // 10240
#define B_BYTES (32 * BROWB)             // 8704
#define STAGE_BYTES (A_BYTES + B_BYTES)  // 18944
#define NSTAGE 3
#define TOK_OFF (NSTAGE * STAGE_BYTES)   // 56832
#define SMEM_BYTES (TOK_OFF + BM * 4)    // 57344 (56 KB) -> 2+ CTAs/SM

// Scratch (28 MB total -- within the known-safe static footprint)
__device__ __half g_xh[(size_t)NT * H];   // x in fp16
__device__ float  g_gu[(size_t)NT * H];   // gate_up outputs (f32), sorted rows
__device__ __half g_h[(size_t)NT * EI];   // silu(gate)*up fp16, sorted rows
__device__ int    g_perm[NT];
__device__ int    g_cnt[NE];
__device__ int    g_off[NE];

// ---------------------------------------------------------------------------
// helpers
// ---------------------------------------------------------------------------
__device__ __forceinline__ float silu(float x) { return x / (1.0f + __expf(-x)); }

__device__ __forceinline__ void cp_async16(void* dst_smem, const void* src) {
    uint32_t dst = (uint32_t)__cvta_generic_to_shared(dst_smem);
    asm volatile("cp.async.cg.shared.global [%0], [%1], 16;\n" :: "r"(dst), "l"(src));
}
#define CP_COMMIT() asm volatile("cp.async.commit_group;\n")
#define CP_WAIT(n)  asm volatile("cp.async.wait_group %0;\n" :: "n"(n))

__device__ __forceinline__ void mma_f16(float* d, const uint32_t* a, const uint32_t* b) {
    asm volatile(
        "mma.sync.aligned.m16n8k16.row.col.f32.f16.f16.f32 "
        "{%0,%1,%2,%3}, {%4,%5,%6,%7}, {%8,%9}, {%0,%1,%2,%3};"
        : "+f"(d[0]), "+f"(d[1]), "+f"(d[2]), "+f"(d[3])
        : "r"(a[0]), "r"(a[1]), "r"(a[2]), "r"(a[3]), "r"(b[0]), "r"(b[1]));
}

__device__ __forceinline__ uint32_t pack2h(float lo, float hi) {
    __half2 h = __floats2half2_rn(lo, hi);
    return *reinterpret_cast<uint32_t*>(&h);
}

// ---------------------------------------------------------------------------
// prep: blocks [0, NXB) convert x -> fp16; block NXB does routing
// (stable counting sort, validated logic).
// ---------------------------------------------------------------------------
#define RT_THREADS 256
#define RT_PER_THR (NT / RT_THREADS)
#define NXB ((NT * H / 8) / 256)   // 2048 blocks

__global__ void prep_kernel(const float* __restrict__ x,
                            const int* __restrict__ token_ids) {
    if (blockIdx.x < NXB) {
        size_t i = ((size_t)blockIdx.x * 256 + threadIdx.x) * 8;
        float4 v0 = *reinterpret_cast<const float4*>(x + i);
        float4 v1 = *reinterpret_cast<const float4*>(x + i + 4);
        uint4 u;
        u.x = pack2h(v0.x, v0.y);
        u.y = pack2h(v0.z, v0.w);
        u.z = pack2h(v1.x, v1.y);
        u.w = pack2h(v1.z, v1.w);
        *reinterpret_cast<uint4*>(g_xh + i) = u;
        return;
    }

    __shared__ int s_hist[RT_THREADS][NE];
    __shared__ int s_pre[RT_THREADS][NE];
    __shared__ int s_total[NE];
    __shared__ int s_exoff[NE];

    const int tid = threadIdx.x;
    const int warp = tid >> 5, lane = tid & 31;

    int loc[NE];
#pragma unroll
    for (int e = 0; e < NE; e++) loc[e] = 0;
    int eid[RT_PER_THR];
#pragma unroll
    for (int i = 0; i < RT_PER_THR; i++) {
        int id = token_ids[tid * RT_PER_THR + i];
        id = min(max(id, 0), NVOCAB - 1);
        int e = id & (NE - 1);
        eid[i] = e;
        loc[e]++;
    }
#pragma unroll
    for (int e = 0; e < NE; e++) s_hist[tid][e] = loc[e];
    __syncthreads();

    if (warp < NE) {
        const int e = warp;
        int run = 0;
        for (int c = 0; c < RT_THREADS; c += 32) {
            int orig = s_hist[c + lane][e];
            int v = orig;
#pragma unroll
            for (int d = 1; d < 32; d <<= 1) {
                int n = __shfl_up_sync(0xFFFFFFFFu, v, d);
                if (lane >= d) v += n;
            }
            s_pre[c + lane][e] = run + v - orig;
            run += __shfl_sync(0xFFFFFFFFu, v, 31);
        }
        if (lane == 31) s_total[e] = run;
    }
    __syncthreads();
    if (tid == 0) {
        int off = 0;
        for (int e = 0; e < NE; e++) {
            s_exoff[e] = off;
            g_off[e] = off;
            g_cnt[e] = s_total[e];
            off += s_total[e];
        }
    }
    __syncthreads();
    int cur[NE];
#pragma unroll
    for (int e = 0; e < NE; e++) cur[e] = s_exoff[e] + s_pre[tid][e];
#pragma unroll
    for (int i = 0; i < RT_PER_THR; i++) {
        int e = eid[i];
        g_perm[cur[e]++] = tid * RT_PER_THR + i;
    }
}

// ---------------------------------------------------------------------------
// Activation: g_h = fp16(silu(gate) * up)
// ---------------------------------------------------------------------------
__global__ __launch_bounds__(256)
void act_kernel() {
    int idx = blockIdx.x * blockDim.x + threadIdx.x;
    int row = idx / (EI / 4);
    int c   = (idx % (EI / 4)) * 4;
    float4 g = *reinterpret_cast<const float4*>(&g_gu[(size_t)row * H + c]);
    float4 u = *reinterpret_cast<const float4*>(&g_gu[(size_t)row * H + c + EI]);
    uint2 o;
    o.x = pack2h(silu(g.x) * u.x, silu(g.y) * u.y);
    o.y = pack2h(silu(g.z) * u.z, silu(g.w) * u.w);
    *reinterpret_cast<uint2*>(g_h + (size_t)row * EI + c) = o;
}

// ---------------------------------------------------------------------------
// GEMM body: C[128,64] = A(fp16 rows) @ W[K][N] (f32, converted per-fragment)
//   A_SRC_ROW(row): const __half* base of A block-row (length KTOT)
//   WP: f32 weight base [KTOT][LDN] for this expert
// ---------------------------------------------------------------------------
#define TC_GEMM_BODY(A_SRC_ROW, WP, LDN, KTOT, EPILOGUE)                            \
    extern __shared__ char smc[];                                                   \
    int* s_tok = (int*)(smc + TOK_OFF);                                             \
    const int tid = threadIdx.x;                                                    \
    if (tid < BM) s_tok[tid] = g_perm[min(base + m0 + tid, NT - 1)];                \
    __syncthreads();                                                                \
    const int warp = tid >> 5, lane = tid & 31;                                     \
    const int wm = (warp & 1) * 64;                                                 \
    const int wn = (warp >> 1) * 16;                                                \
    const int grp = lane >> 2, quad = lane & 3;                                     \
    const int a_row = tid >> 2, a_ch = tid & 3;    /* A: 2 passes, +64 rows */      \
    const int b_row = tid >> 4, b_ch = tid & 15;   /* B: 2 passes, +16 rows */      \
    float acc[4][2][4];                                                             \
    _Pragma("unroll")                                                               \
    for (int i = 0; i < 4; i++)                                                     \
        _Pragma("unroll")                                                           \
        for (int j = 0; j < 2; j++)                                                 \
            _Pragma("unroll")                                                       \
            for (int r = 0; r < 4; r++) acc[i][j][r] = 0.f;                         \
    auto stage = [&](int kt0, int buf) {                                            \
        char* sa = smc + buf * STAGE_BYTES;                                         \
        char* sb = sa + A_BYTES;                                                    \
        _Pragma("unroll")                                                           \
        for (int i = 0; i < 2; i++) {                                               \
            int row = a_row + i * 64;                                               \
            cp_async16(sa + row * AROWB + a_ch * 16,                                \
                       A_SRC_ROW(row) + kt0 + a_ch * 8);                            \
        }                                                                           \
        _Pragma("unroll")                                                           \
        for (int i = 0; i < 2; i++) {                                               \
            int k = b_row + i * 16;                                                 \
            cp_async16(sb + k * BROWB + b_ch * 16,                                  \
                       (WP) + (size_t)(kt0 + k) * (LDN) + n0 + b_ch * 4);           \
        }                                                                           \
        CP_COMMIT();                                                                \
    };                                                                              \
    const int KT = (KTOT) / BK;                                                     \
    stage(0, 0); stage(BK, 1);                                                      \
    for (int kt = 0; kt < KT; kt++) {                                               \
        if (kt < KT - 1) { CP_WAIT(1); } else { CP_WAIT(0); }                       \
        __syncthreads();                                                            \
        if (kt + 2 < KT) stage((kt + 2) * BK, (kt + 2) % NSTAGE);                   \
        const char*  sa  = smc + (kt % NSTAGE) * STAGE_BYTES;                       \
        const float* sbf = (const float*)(sa + A_BYTES);                            \
        _Pragma("unroll")                                                           \
        for (int ks = 0; ks < 2; ks++) {                                            \
            uint32_t af[4][4], bf[2][2];                                            \
            _Pragma("unroll")                                                       \
            for (int mf = 0; mf < 4; mf++) {                                        \
                const char* r = sa + (wm + mf * 16 + grp) * AROWB                   \
                                   + ks * 32 + quad * 4;                            \
                af[mf][0] = *(const uint32_t*)(r);                                  \
                af[mf][1] = *(const uint32_t*)(r + 8 * AROWB);                      \
                af[mf][2] = *(const uint32_t*)(r + 16);                             \
                af[mf][3] = *(const uint32_t*)(r + 8 * AROWB + 16);                 \
            }                                                                       \
            _Pragma("unroll")                                                       \
            for (int nf = 0; nf < 2; nf++) {                                        \
                int n  = wn + nf * 8 + grp;                                         \
                int k0 = ks * 16 + quad * 2;                                        \
                bf[nf][0] = pack2h(sbf[(size_t)k0 * 68 + n],                        \
                                   sbf[(size_t)(k0 + 1) * 68 + n]);                 \
                bf[nf][1] = pack2h(sbf[(size_t)(k0 + 8) * 68 + n],                  \
                                   sbf[(size_t)(k0 + 9) * 68 + n]);                 \
            }                                                                       \
            _Pragma("unroll")                                                       \
            for (int mf = 0; mf < 4; mf++)                                          \
                _Pragma("unroll")                                                   \
                for (int nf = 0; nf < 2; nf++)                                      \
                    mma_f16(acc[mf][nf], af[mf], bf[nf]);                           \
        }                                                                           \
    }                                                                               \
    const int mrem = cnt - m0;                                                      \
    _Pragma("unroll")                                                               \
    for (int mf = 0; mf < 4; mf++) {                                                \
        int r0 = wm + mf * 16 + grp;                                                \
        int r1 = r0 + 8;                                                            \
        _Pragma("unroll")                                                           \
        for (int nf = 0; nf < 2; nf++) {                                            \
            int c = n0 + wn + nf * 8 + quad * 2;                                    \
            EPILOGUE                                                                \
        }                                                                           \
    }

// GEMM1: g_gu[base+m0+r, :] = xh(token rows) @ gate_up[e]   (K=H, N=2*EI)
__global__ __launch_bounds__(256, 2)
void gemm1_kernel(const float* __restrict__ gate_up) {
    const int e   = blockIdx.z;
    const int cnt = g_cnt[e];
    const int m0  = blockIdx.y * BM;
    if (m0 >= cnt) return;
    const int base = g_off[e];
    const int n0   = blockIdx.x * BN;
    const float* Wp = gate_up + (size_t)e * H * (2 * EI);

#define A1_SRC(row) (g_xh + (size_t)s_tok[row] * H)
#define EPI1                                                                        \
    if (r0 < mrem)                                                                  \
        *reinterpret_cast<float2*>(&g_gu[(size_t)(base + m0 + r0) * H + c]) =       \
            make_float2(acc[mf][nf][0], acc[mf][nf][1]);                            \
    if (r1 < mrem)                                                                  \
        *reinterpret_cast<float2*>(&g_gu[(size_t)(base + m0 + r1) * H + c]) =       \
            make_float2(acc[mf][nf][2], acc[mf][nf][3]);

    TC_GEMM_BODY(A1_SRC, Wp, 2 * EI, H, EPI1)
#undef A1_SRC
#undef EPI1
}

// GEMM2: out[tok, :] = g_h(sorted rows) @ down[e]   (K=EI, N=H)
__global__ __launch_bounds__(256, 2)
void gemm2_kernel(const float* __restrict__ down, float* __restrict__ out) {
    const int e   = blockIdx.z;
    const int cnt = g_cnt[e];
    const int m0  = blockIdx.y * BM;
    if (m0 >= cnt) return;
    const int base = g_off[e];
    const int n0   = blockIdx.x * BN;
    const float* Wp = down + (size_t)e * EI * H;

#define A2_SRC(row) (g_h + (size_t)min(base + m0 + (row), NT - 1) * EI)
#define EPI2                                                                        \
    if (r0 < mrem)                                                                  \
        *reinterpret_cast<float2*>(&out[(size_t)s_tok[r0] * H + c]) =               \
            make_float2(acc[mf][nf][0], acc[mf][nf][1]);                            \
    if (r1 < mrem)                                                                  \
        *reinterpret_cast<float2*>(&out[(size_t)s_tok[r1] * H + c]) =               \
            make_float2(acc[mf][nf][2], acc[mf][nf][3]);

    TC_GEMM_BODY(A2_SRC, Wp, H, EI, EPI2)
#undef A2_SRC
#undef EPI2
}

// ---------------------------------------------------------------------------
// Launch
// ---------------------------------------------------------------------------
extern "C" void kernel_launch(void* const* d_in, const int* in_sizes, int n_in,
                              void* d_out, int out_size) {
    const float* x         = (const float*)d_in[0];
    const int*   token_ids = (const int*)d_in[1];
    const float* gate_up   = (const float*)d_in[2];
    const float* down      = (const float*)d_in[3];
    float*       out       = (float*)d_out;

    cudaFuncSetAttribute(gemm1_kernel, cudaFuncAttributeMaxDynamicSharedMemorySize, SMEM_BYTES);
    cudaFuncSetAttribute(gemm2_kernel, cudaFuncAttributeMaxDynamicSharedMemorySize, SMEM_BYTES);

    prep_kernel<<<NXB + 1, 256>>>(x, token_ids);

    dim3 grid1(2 * EI / BN, NT / BM, NE);   // 32 x 16 x 8, early-exit on counts
    gemm1_kernel<<<grid1, 256, SMEM_BYTES>>>(gate_up);
    act_kernel<<<(NT * EI / 4) / 256, 256>>>();
    dim3 grid2(H / BN, NT / BM, NE);        // 32 x 16 x 8
    gemm2_kernel<<<grid2, 256, SMEM_BYTES>>>(down, out);
}

// round 9
// speedup vs baseline: 2.7969x; 1.1099x over previous
#include <cuda_runtime.h>
#include <cuda_fp16.h>
#include <cstdint>

// Problem constants
#define H      2048
#define EI     1024
#define NE     8
#define NT     2048
#define NVOCAB 32000

// GEMM tiling: 128 x 64 tile, BK = 32 k-halves per stage, 8 warps (2M x 4N)
#define BM 128
#define BN 64
#define BK 32

// smem per stage: A fp16 [128][32] stride 80B, B f32 [32][64] stride 272B
#define AROWB 80
#define BROWB 272
#define A_BYTES (128 * AROWB)            // 10240
#define B_BYTES (32 * BROWB)             // 8704
#define STAGE_BYTES (A_BYTES + B_BYTES)  // 18944
#define NSTAGE 4
#define TOK_OFF (NSTAGE * STAGE_BYTES)   // 75776
#define SMEM_BYTES (TOK_OFF + BM * 4)    // 76288 -> 2 CTAs/SM

// Scratch (28 MB total)
__device__ __half g_xh[(size_t)NT * H];
__device__ float  g_gu[(size_t)NT * H];
__device__ __half g_h[(size_t)NT * EI];
__device__ int    g_perm[NT];
__device__ int    g_cnt[NE];
__device__ int    g_off[NE];

// ---------------------------------------------------------------------------
// helpers
// ---------------------------------------------------------------------------
__device__ __forceinline__ float silu(float x) { return x / (1.0f + __expf(-x)); }

__device__ __forceinline__ void cp_async16(void* dst_smem, const void* src) {
    uint32_t dst = (uint32_t)__cvta_generic_to_shared(dst_smem);
    asm volatile("cp.async.cg.shared.global [%0], [%1], 16;\n" :: "r"(dst), "l"(src));
}
#define CP_COMMIT() asm volatile("cp.async.commit_group;\n")
#define CP_WAIT(n)  asm volatile("cp.async.wait_group %0;\n" :: "n"(n))

__device__ __forceinline__ void mma_f16(float* d, const uint32_t* a, const uint32_t* b) {
    asm volatile(
        "mma.sync.aligned.m16n8k16.row.col.f32.f16.f16.f32 "
        "{%0,%1,%2,%3}, {%4,%5,%6,%7}, {%8,%9}, {%0,%1,%2,%3};"
        : "+f"(d[0]), "+f"(d[1]), "+f"(d[2]), "+f"(d[3])
        : "r"(a[0]), "r"(a[1]), "r"(a[2]), "r"(a[3]), "r"(b[0]), "r"(b[1]));
}

__device__ __forceinline__ void ldsm_x4(uint32_t* r, uint32_t addr) {
    asm volatile("ldmatrix.sync.aligned.m8n8.x4.shared.b16 {%0,%1,%2,%3}, [%4];"
                 : "=r"(r[0]), "=r"(r[1]), "=r"(r[2]), "=r"(r[3]) : "r"(addr));
}

__device__ __forceinline__ uint32_t pack2h(float lo, float hi) {
    __half2 h = __floats2half2_rn(lo, hi);
    return *reinterpret_cast<uint32_t*>(&h);
}

// ---------------------------------------------------------------------------
// prep: blocks [0, NXB) convert x -> fp16; block NXB does routing.
// ---------------------------------------------------------------------------
#define RT_THREADS 256
#define RT_PER_THR (NT / RT_THREADS)
#define NXB ((NT * H / 8) / 256)

__global__ void prep_kernel(const float* __restrict__ x,
                            const int* __restrict__ token_ids) {
    if (blockIdx.x < NXB) {
        size_t i = ((size_t)blockIdx.x * 256 + threadIdx.x) * 8;
        float4 v0 = *reinterpret_cast<const float4*>(x + i);
        float4 v1 = *reinterpret_cast<const float4*>(x + i + 4);
        uint4 u;
        u.x = pack2h(v0.x, v0.y);
        u.y = pack2h(v0.z, v0.w);
        u.z = pack2h(v1.x, v1.y);
        u.w = pack2h(v1.z, v1.w);
        *reinterpret_cast<uint4*>(g_xh + i) = u;
        return;
    }

    __shared__ int s_hist[RT_THREADS][NE];
    __shared__ int s_pre[RT_THREADS][NE];
    __shared__ int s_total[NE];
    __shared__ int s_exoff[NE];

    const int tid = threadIdx.x;
    const int warp = tid >> 5, lane = tid & 31;

    int loc[NE];
#pragma unroll
    for (int e = 0; e < NE; e++) loc[e] = 0;
    int eid[RT_PER_THR];
#pragma unroll
    for (int i = 0; i < RT_PER_THR; i++) {
        int id = token_ids[tid * RT_PER_THR + i];
        id = min(max(id, 0), NVOCAB - 1);
        int e = id & (NE - 1);
        eid[i] = e;
        loc[e]++;
    }
#pragma unroll
    for (int e = 0; e < NE; e++) s_hist[tid][e] = loc[e];
    __syncthreads();

    if (warp < NE) {
        const int e = warp;
        int run = 0;
        for (int c = 0; c < RT_THREADS; c += 32) {
            int orig = s_hist[c + lane][e];
            int v = orig;
#pragma unroll
            for (int d = 1; d < 32; d <<= 1) {
                int n = __shfl_up_sync(0xFFFFFFFFu, v, d);
                if (lane >= d) v += n;
            }
            s_pre[c + lane][e] = run + v - orig;
            run += __shfl_sync(0xFFFFFFFFu, v, 31);
        }
        if (lane == 31) s_total[e] = run;
    }
    __syncthreads();
    if (tid == 0) {
        int off = 0;
        for (int e = 0; e < NE; e++) {
            s_exoff[e] = off;
            g_off[e] = off;
            g_cnt[e] = s_total[e];
            off += s_total[e];
        }
    }
    __syncthreads();
    int cur[NE];
#pragma unroll
    for (int e = 0; e < NE; e++) cur[e] = s_exoff[e] + s_pre[tid][e];
#pragma unroll
    for (int i = 0; i < RT_PER_THR; i++) {
        int e = eid[i];
        g_perm[cur[e]++] = tid * RT_PER_THR + i;
    }
}

// ---------------------------------------------------------------------------
// Activation
// ---------------------------------------------------------------------------
__global__ __launch_bounds__(256)
void act_kernel() {
    int idx = blockIdx.x * blockDim.x + threadIdx.x;
    int row = idx / (EI / 4);
    int c   = (idx % (EI / 4)) * 4;
    float4 g = *reinterpret_cast<const float4*>(&g_gu[(size_t)row * H + c]);
    float4 u = *reinterpret_cast<const float4*>(&g_gu[(size_t)row * H + c + EI]);
    uint2 o;
    o.x = pack2h(silu(g.x) * u.x, silu(g.y) * u.y);
    o.y = pack2h(silu(g.z) * u.z, silu(g.w) * u.w);
    *reinterpret_cast<uint2*>(g_h + (size_t)row * EI + c) = o;
}

// ---------------------------------------------------------------------------
// GEMM body: C[128,64] = A(fp16 rows) @ W[K][N] (f32 streamed, fragment-pack)
// 4-stage pipeline, prefetch issued BEFORE the wait (true distance 2).
// A fragments via ldmatrix.x4.
// ---------------------------------------------------------------------------
#define TC_GEMM_BODY(A_SRC_ROW, WP, LDN, KTOT, EPILOGUE)                            \
    extern __shared__ char smc[];                                                   \
    int* s_tok = (int*)(smc + TOK_OFF);                                             \
    const int tid = threadIdx.x;                                                    \
    if (tid < BM) s_tok[tid] = g_perm[min(base + m0 + tid, NT - 1)];                \
    __syncthreads();                                                                \
    const int warp = tid >> 5, lane = tid & 31;                                     \
    const int wm = (warp & 1) * 64;                                                 \
    const int wn = (warp >> 1) * 16;                                                \
    const int grp = lane >> 2, quad = lane & 3;                                     \
    const int a_row = tid >> 2, a_ch = tid & 3;                                     \
    const int b_row = tid >> 4, b_ch = tid & 15;                                    \
    /* ldmatrix lane addressing: row = wm + (lane&15) + mf*16, col = (lane>>4)*16 */\
    const int lm_row = wm + (lane & 15);                                            \
    const int lm_col = (lane >> 4) * 16;                                            \
    float acc[4][2][4];                                                             \
    _Pragma("unroll")                                                               \
    for (int i = 0; i < 4; i++)                                                     \
        _Pragma("unroll")                                                           \
        for (int j = 0; j < 2; j++)                                                 \
            _Pragma("unroll")                                                       \
            for (int r = 0; r < 4; r++) acc[i][j][r] = 0.f;                         \
    auto stage = [&](int kt0, int buf) {                                            \
        char* sa = smc + buf * STAGE_BYTES;                                         \
        char* sb = sa + A_BYTES;                                                    \
        _Pragma("unroll")                                                           \
        for (int i = 0; i < 2; i++) {                                               \
            int row = a_row + i * 64;                                               \
            cp_async16(sa + row * AROWB + a_ch * 16,                                \
                       A_SRC_ROW(row) + kt0 + a_ch * 8);                            \
        }                                                                           \
        _Pragma("unroll")                                                           \
        for (int i = 0; i < 2; i++) {                                               \
            int k = b_row + i * 16;                                                 \
            cp_async16(sb + k * BROWB + b_ch * 16,                                  \
                       (WP) + (size_t)(kt0 + k) * (LDN) + n0 + b_ch * 4);           \
        }                                                                           \
        CP_COMMIT();                                                                \
    };                                                                              \
    const int KT = (KTOT) / BK;                                                     \
    stage(0, 0); stage(BK, 1);                                                      \
    for (int kt = 0; kt < KT; kt++) {                                               \
        if (kt + 2 < KT) { stage((kt + 2) * BK, (kt + 2) & 3); CP_WAIT(2); }        \
        else if (kt + 1 < KT) { CP_WAIT(1); }                                       \
        else { CP_WAIT(0); }                                                        \
        __syncthreads();                                                            \
        const char*  sa  = smc + (kt & 3) * STAGE_BYTES;                            \
        const float* sbf = (const float*)(sa + A_BYTES);                            \
        const uint32_t sa_u = (uint32_t)__cvta_generic_to_shared(sa);               \
        _Pragma("unroll")                                                           \
        for (int ks = 0; ks < 2; ks++) {                                            \
            uint32_t af[4][4], bf[2][2];                                            \
            _Pragma("unroll")                                                       \
            for (int mf = 0; mf < 4; mf++)                                          \
                ldsm_x4(af[mf], sa_u + (uint32_t)((lm_row + mf * 16) * AROWB        \
                                                  + ks * 32 + lm_col));             \
            _Pragma("unroll")                                                       \
            for (int nf = 0; nf < 2; nf++) {                                        \
                int n  = wn + nf * 8 + grp;                                         \
                int k0 = ks * 16 + quad * 2;                                        \
                bf[nf][0] = pack2h(sbf[(size_t)k0 * 68 + n],                        \
                                   sbf[(size_t)(k0 + 1) * 68 + n]);                 \
                bf[nf][1] = pack2h(sbf[(size_t)(k0 + 8) * 68 + n],                  \
                                   sbf[(size_t)(k0 + 9) * 68 + n]);                 \
            }                                                                       \
            _Pragma("unroll")                                                       \
            for (int mf = 0; mf < 4; mf++)                                          \
                _Pragma("unroll")                                                   \
                for (int nf = 0; nf < 2; nf++)                                      \
                    mma_f16(acc[mf][nf], af[mf], bf[nf]);                           \
        }                                                                           \
    }                                                                               \
    const int mrem = cnt - m0;                                                      \
    _Pragma("unroll")                                                               \
    for (int mf = 0; mf < 4; mf++) {                                                \
        int r0 = wm + mf * 16 + grp;                                                \
        int r1 = r0 + 8;                                                            \
        _Pragma("unroll")                                                           \
        for (int nf = 0; nf < 2; nf++) {                                            \
            int c = n0 + wn + nf * 8 + quad * 2;                                    \
            EPILOGUE                                                                \
        }                                                                           \
    }

// GEMM1: g_gu[base+m0+r, :] = xh(token rows) @ gate_up[e]   (K=H, N=2*EI)
__global__ __launch_bounds__(256, 2)
void gemm1_kernel(const float* __restrict__ gate_up) {
    const int e   = blockIdx.z;
    const int cnt = g_cnt[e];
    const int m0  = blockIdx.y * BM;
    if (m0 >= cnt) return;
    const int base = g_off[e];
    const int n0   = blockIdx.x * BN;
    const float* Wp = gate_up + (size_t)e * H * (2 * EI);

#define A1_SRC(row) (g_xh + (size_t)s_tok[row] * H)
#define EPI1                                                                        \
    if (r0 < mrem)                                                                  \
        *reinterpret_cast<float2*>(&g_gu[(size_t)(base + m0 + r0) * H + c]) =       \
            make_float2(acc[mf][nf][0], acc[mf][nf][1]);                            \
    if (r1 < mrem)                                                                  \
        *reinterpret_cast<float2*>(&g_gu[(size_t)(base + m0 + r1) * H + c]) =       \
            make_float2(acc[mf][nf][2], acc[mf][nf][3]);

    TC_GEMM_BODY(A1_SRC, Wp, 2 * EI, H, EPI1)
#undef A1_SRC
#undef EPI1
}

// GEMM2: out[tok, :] = g_h(sorted rows) @ down[e]   (K=EI, N=H)
__global__ __launch_bounds__(256, 2)
void gemm2_kernel(const float* __restrict__ down, float* __restrict__ out) {
    const int e   = blockIdx.z;
    const int cnt = g_cnt[e];
    const int m0  = blockIdx.y * BM;
    if (m0 >= cnt) return;
    const int base = g_off[e];
    const int n0   = blockIdx.x * BN;
    const float* Wp = down + (size_t)e * EI * H;

#define A2_SRC(row) (g_h + (size_t)min(base + m0 + (row), NT - 1) * EI)
#define EPI2                                                                        \
    if (r0 < mrem)                                                                  \
        *reinterpret_cast<float2*>(&out[(size_t)s_tok[r0] * H + c]) =               \
            make_float2(acc[mf][nf][0], acc[mf][nf][1]);                            \
    if (r1 < mrem)                                                                  \
        *reinterpret_cast<float2*>(&out[(size_t)s_tok[r1] * H + c]) =               \
            make_float2(acc[mf][nf][2], acc[mf][nf][3]);

    TC_GEMM_BODY(A2_SRC, Wp, H, EI, EPI2)
#undef A2_SRC
#undef EPI2
}

// ---------------------------------------------------------------------------
// Launch
// ---------------------------------------------------------------------------
extern "C" void kernel_launch(void* const* d_in, const int* in_sizes, int n_in,
                              void* d_out, int out_size) {
    const float* x         = (const float*)d_in[0];
    const int*   token_ids = (const int*)d_in[1];
    const float* gate_up   = (const float*)d_in[2];
    const float* down      = (const float*)d_in[3];
    float*       out       = (float*)d_out;

    cudaFuncSetAttribute(gemm1_kernel, cudaFuncAttributeMaxDynamicSharedMemorySize, SMEM_BYTES);
    cudaFuncSetAttribute(gemm2_kernel, cudaFuncAttributeMaxDynamicSharedMemorySize, SMEM_BYTES);

    prep_kernel<<<NXB + 1, 256>>>(x, token_ids);

    dim3 grid1(2 * EI / BN, NT / BM, NE);
    gemm1_kernel<<<grid1, 256, SMEM_BYTES>>>(gate_up);
    act_kernel<<<(NT * EI / 4) / 256, 256>>>();
    dim3 grid2(H / BN, NT / BM, NE);
    gemm2_kernel<<<grid2, 256, SMEM_BYTES>>>(down, out);
}

// round 10
// speedup vs baseline: 2.8236x; 1.0095x over previous
#include <cuda_runtime.h>
#include <cuda_fp16.h>
#include <cstdint>

// Problem constants
#define H      2048
#define EI     1024
#define NE     8
#define NT     2048
#define NVOCAB 32000

// GEMM tiling: 128 x 64 tile, BK = 32 k-halves per stage, 8 warps (2M x 4N)
#define BM 128
#define BN 64
#define BK 32

// smem per stage: A fp16 [128][32] stride 80B, B f32 [32][64] stride 272B
#define AROWB 80
#define BROWB 272
#define A_BYTES (128 * AROWB)            // 10240
#define B_BYTES (32 * BROWB)             // 8704
#define STAGE_BYTES (A_BYTES + B_BYTES)  // 18944
#define NSTAGE 3
#define TOK_OFF (NSTAGE * STAGE_BYTES)   // 56832
#define SMEM_BYTES (TOK_OFF + BM * 4)    // 57344 -> 3 CTAs/SM

// Scratch (20 MB total)
__device__ __half g_xh[(size_t)NT * H];   // x fp16
__device__ __half g_gu[(size_t)NT * H];   // gate_up outputs fp16, sorted rows
__device__ __half g_h[(size_t)NT * EI];   // silu(gate)*up fp16, sorted rows
__device__ int    g_perm[NT];
__device__ int    g_cnt[NE];
__device__ int    g_off[NE];

// ---------------------------------------------------------------------------
// helpers
// ---------------------------------------------------------------------------
__device__ __forceinline__ float silu(float x) { return x / (1.0f + __expf(-x)); }

__device__ __forceinline__ void cp_async16(void* dst_smem, const void* src) {
    uint32_t dst = (uint32_t)__cvta_generic_to_shared(dst_smem);
    asm volatile("cp.async.cg.shared.global [%0], [%1], 16;\n" :: "r"(dst), "l"(src));
}
#define CP_COMMIT() asm volatile("cp.async.commit_group;\n")
#define CP_WAIT(n)  asm volatile("cp.async.wait_group %0;\n" :: "n"(n))

__device__ __forceinline__ void mma_f16(float* d, const uint32_t* a, const uint32_t* b) {
    asm volatile(
        "mma.sync.aligned.m16n8k16.row.col.f32.f16.f16.f32 "
        "{%0,%1,%2,%3}, {%4,%5,%6,%7}, {%8,%9}, {%0,%1,%2,%3};"
        : "+f"(d[0]), "+f"(d[1]), "+f"(d[2]), "+f"(d[3])
        : "r"(a[0]), "r"(a[1]), "r"(a[2]), "r"(a[3]), "r"(b[0]), "r"(b[1]));
}

__device__ __forceinline__ void ldsm_x4(uint32_t* r, uint32_t addr) {
    asm volatile("ldmatrix.sync.aligned.m8n8.x4.shared.b16 {%0,%1,%2,%3}, [%4];"
                 : "=r"(r[0]), "=r"(r[1]), "=r"(r[2]), "=r"(r[3]) : "r"(addr));
}

__device__ __forceinline__ uint32_t pack2h(float lo, float hi) {
    __half2 h = __floats2half2_rn(lo, hi);
    return *reinterpret_cast<uint32_t*>(&h);
}

// ---------------------------------------------------------------------------
// prep: blocks [0, NXB) convert x -> fp16; block NXB does routing.
// ---------------------------------------------------------------------------
#define RT_THREADS 256
#define RT_PER_THR (NT / RT_THREADS)
#define NXB ((NT * H / 8) / 256)

__global__ void prep_kernel(const float* __restrict__ x,
                            const int* __restrict__ token_ids) {
    if (blockIdx.x < NXB) {
        size_t i = ((size_t)blockIdx.x * 256 + threadIdx.x) * 8;
        float4 v0 = *reinterpret_cast<const float4*>(x + i);
        float4 v1 = *reinterpret_cast<const float4*>(x + i + 4);
        uint4 u;
        u.x = pack2h(v0.x, v0.y);
        u.y = pack2h(v0.z, v0.w);
        u.z = pack2h(v1.x, v1.y);
        u.w = pack2h(v1.z, v1.w);
        *reinterpret_cast<uint4*>(g_xh + i) = u;
        return;
    }

    __shared__ int s_hist[RT_THREADS][NE];
    __shared__ int s_pre[RT_THREADS][NE];
    __shared__ int s_total[NE];
    __shared__ int s_exoff[NE];

    const int tid = threadIdx.x;
    const int warp = tid >> 5, lane = tid & 31;

    int loc[NE];
#pragma unroll
    for (int e = 0; e < NE; e++) loc[e] = 0;
    int eid[RT_PER_THR];
#pragma unroll
    for (int i = 0; i < RT_PER_THR; i++) {
        int id = token_ids[tid * RT_PER_THR + i];
        id = min(max(id, 0), NVOCAB - 1);
        int e = id & (NE - 1);
        eid[i] = e;
        loc[e]++;
    }
#pragma unroll
    for (int e = 0; e < NE; e++) s_hist[tid][e] = loc[e];
    __syncthreads();

    if (warp < NE) {
        const int e = warp;
        int run = 0;
        for (int c = 0; c < RT_THREADS; c += 32) {
            int orig = s_hist[c + lane][e];
            int v = orig;
#pragma unroll
            for (int d = 1; d < 32; d <<= 1) {
                int n = __shfl_up_sync(0xFFFFFFFFu, v, d);
                if (lane >= d) v += n;
            }
            s_pre[c + lane][e] = run + v - orig;
            run += __shfl_sync(0xFFFFFFFFu, v, 31);
        }
        if (lane == 31) s_total[e] = run;
    }
    __syncthreads();
    if (tid == 0) {
        int off = 0;
        for (int e = 0; e < NE; e++) {
            s_exoff[e] = off;
            g_off[e] = off;
            g_cnt[e] = s_total[e];
            off += s_total[e];
        }
    }
    __syncthreads();
    int cur[NE];
#pragma unroll
    for (int e = 0; e < NE; e++) cur[e] = s_exoff[e] + s_pre[tid][e];
#pragma unroll
    for (int i = 0; i < RT_PER_THR; i++) {
        int e = eid[i];
        g_perm[cur[e]++] = tid * RT_PER_THR + i;
    }
}

// ---------------------------------------------------------------------------
// Activation: g_h = fp16(silu(gate) * up), reading fp16 g_gu
// ---------------------------------------------------------------------------
__global__ __launch_bounds__(256)
void act_kernel() {
    int idx = blockIdx.x * blockDim.x + threadIdx.x;
    int row = idx / (EI / 4);
    int c   = (idx % (EI / 4)) * 4;
    const __half* gu = g_gu + (size_t)row * H;
    uint2 gp = *reinterpret_cast<const uint2*>(gu + c);
    uint2 up = *reinterpret_cast<const uint2*>(gu + c + EI);
    float2 g0 = __half22float2(*reinterpret_cast<__half2*>(&gp.x));
    float2 g1 = __half22float2(*reinterpret_cast<__half2*>(&gp.y));
    float2 u0 = __half22float2(*reinterpret_cast<__half2*>(&up.x));
    float2 u1 = __half22float2(*reinterpret_cast<__half2*>(&up.y));
    uint2 o;
    o.x = pack2h(silu(g0.x) * u0.x, silu(g0.y) * u0.y);
    o.y = pack2h(silu(g1.x) * u1.x, silu(g1.y) * u1.y);
    *reinterpret_cast<uint2*>(g_h + (size_t)row * EI + c) = o;
}

// ---------------------------------------------------------------------------
// GEMM body: C[128,64] = A(fp16 rows) @ W[K][N] (f32 streamed, fragment-pack)
// 3-stage pipeline; stage issued AFTER the barrier (no buffer race at mod-3),
// effective prefetch distance 2. A fragments via ldmatrix.x4.
// ---------------------------------------------------------------------------
#define TC_GEMM_BODY(A_SRC_ROW, WP, LDN, KTOT, EPILOGUE)                            \
    extern __shared__ char smc[];                                                   \
    int* s_tok = (int*)(smc + TOK_OFF);                                             \
    const int tid = threadIdx.x;                                                    \
    if (tid < BM) s_tok[tid] = g_perm[min(base + m0 + tid, NT - 1)];                \
    __syncthreads();                                                                \
    const int warp = tid >> 5, lane = tid & 31;                                     \
    const int wm = (warp & 1) * 64;                                                 \
    const int wn = (warp >> 1) * 16;                                                \
    const int grp = lane >> 2, quad = lane & 3;                                     \
    const int a_row = tid >> 2, a_ch = tid & 3;                                     \
    const int b_row = tid >> 4, b_ch = tid & 15;                                    \
    const int lm_row = wm + (lane & 15);                                            \
    const int lm_col = (lane >> 4) * 16;                                            \
    float acc[4][2][4];                                                             \
    _Pragma("unroll")                                                               \
    for (int i = 0; i < 4; i++)                                                     \
        _Pragma("unroll")                                                           \
        for (int j = 0; j < 2; j++)                                                 \
            _Pragma("unroll")                                                       \
            for (int r = 0; r < 4; r++) acc[i][j][r] = 0.f;                         \
    auto stage = [&](int kt0, int buf) {                                            \
        char* sa = smc + buf * STAGE_BYTES;                                         \
        char* sb = sa + A_BYTES;                                                    \
        _Pragma("unroll")                                                           \
        for (int i = 0; i < 2; i++) {                                               \
            int row = a_row + i * 64;                                               \
            cp_async16(sa + row * AROWB + a_ch * 16,                                \
                       A_SRC_ROW(row) + kt0 + a_ch * 8);                            \
        }                                                                           \
        _Pragma("unroll")                                                           \
        for (int i = 0; i < 2; i++) {                                               \
            int k = b_row + i * 16;                                                 \
            cp_async16(sb + k * BROWB + b_ch * 16,                                  \
                       (WP) + (size_t)(kt0 + k) * (LDN) + n0 + b_ch * 4);           \
        }                                                                           \
        CP_COMMIT();                                                                \
    };                                                                              \
    const int KT = (KTOT) / BK;                                                     \
    stage(0, 0); stage(BK, 1);                                                      \
    for (int kt = 0; kt < KT; kt++) {                                               \
        if (kt + 1 < KT) { CP_WAIT(1); } else { CP_WAIT(0); }                       \
        __syncthreads();                                                            \
        if (kt + 2 < KT) stage((kt + 2) * BK, (kt + 2) % NSTAGE);                   \
        const char*  sa  = smc + (kt % NSTAGE) * STAGE_BYTES;                       \
        const float* sbf = (const float*)(sa + A_BYTES);                            \
        const uint32_t sa_u = (uint32_t)__cvta_generic_to_shared(sa);               \
        _Pragma("unroll")                                                           \
        for (int ks = 0; ks < 2; ks++) {                                            \
            uint32_t af[4][4], bf[2][2];                                            \
            _Pragma("unroll")                                                       \
            for (int mf = 0; mf < 4; mf++)                                          \
                ldsm_x4(af[mf], sa_u + (uint32_t)((lm_row + mf * 16) * AROWB        \
                                                  + ks * 32 + lm_col));             \
            _Pragma("unroll")                                                       \
            for (int nf = 0; nf < 2; nf++) {                                        \
                int n  = wn + nf * 8 + grp;                                         \
                int k0 = ks * 16 + quad * 2;                                        \
                bf[nf][0] = pack2h(sbf[(size_t)k0 * 68 + n],                        \
                                   sbf[(size_t)(k0 + 1) * 68 + n]);                 \
                bf[nf][1] = pack2h(sbf[(size_t)(k0 + 8) * 68 + n],                  \
                                   sbf[(size_t)(k0 + 9) * 68 + n]);                 \
            }                                                                       \
            _Pragma("unroll")                                                       \
            for (int mf = 0; mf < 4; mf++)                                          \
                _Pragma("unroll")                                                   \
                for (int nf = 0; nf < 2; nf++)                                      \
                    mma_f16(acc[mf][nf], af[mf], bf[nf]);                           \
        }                                                                           \
    }                                                                               \
    const int mrem = cnt - m0;                                                      \
    _Pragma("unroll")                                                               \
    for (int mf = 0; mf < 4; mf++) {                                                \
        int r0 = wm + mf * 16 + grp;                                                \
        int r1 = r0 + 8;                                                            \
        _Pragma("unroll")                                                           \
        for (int nf = 0; nf < 2; nf++) {                                            \
            int c = n0 + wn + nf * 8 + quad * 2;                                    \
            EPILOGUE                                                                \
        }                                                                           \
    }

// GEMM1: g_gu[base+m0+r, :] = xh(token rows) @ gate_up[e]   (K=H, N=2*EI)
// Output packed fp16.
__global__ __launch_bounds__(256, 3)
void gemm1_kernel(const float* __restrict__ gate_up) {
    const int e   = blockIdx.z;
    const int cnt = g_cnt[e];
    const int m0  = blockIdx.y * BM;
    if (m0 >= cnt) return;
    const int base = g_off[e];
    const int n0   = blockIdx.x * BN;
    const float* Wp = gate_up + (size_t)e * H * (2 * EI);

#define A1_SRC(row) (g_xh + (size_t)s_tok[row] * H)
#define EPI1                                                                        \
    if (r0 < mrem)                                                                  \
        *reinterpret_cast<uint32_t*>(&g_gu[(size_t)(base + m0 + r0) * H + c]) =     \
            pack2h(acc[mf][nf][0], acc[mf][nf][1]);                                 \
    if (r1 < mrem)                                                                  \
        *reinterpret_cast<uint32_t*>(&g_gu[(size_t)(base + m0 + r1) * H + c]) =     \
            pack2h(acc[mf][nf][2], acc[mf][nf][3]);

    TC_GEMM_BODY(A1_SRC, Wp, 2 * EI, H, EPI1)
#undef A1_SRC
#undef EPI1
}

// GEMM2: out[tok, :] = g_h(sorted rows) @ down[e]   (K=EI, N=H)
__global__ __launch_bounds__(256, 3)
void gemm2_kernel(const float* __restrict__ down, float* __restrict__ out) {
    const int e   = blockIdx.z;
    const int cnt = g_cnt[e];
    const int m0  = blockIdx.y * BM;
    if (m0 >= cnt) return;
    const int base = g_off[e];
    const int n0   = blockIdx.x * BN;
    const float* Wp = down + (size_t)e * EI * H;

#define A2_SRC(row) (g_h + (size_t)min(base + m0 + (row), NT - 1) * EI)
#define EPI2                                                                        \
    if (r0 < mrem)                                                                  \
        *reinterpret_cast<float2*>(&out[(size_t)s_tok[r0] * H + c]) =               \
            make_float2(acc[mf][nf][0], acc[mf][nf][1]);                            \
    if (r1 < mrem)                                                                  \
        *reinterpret_cast<float2*>(&out[(size_t)s_tok[r1] * H + c]) =               \
            make_float2(acc[mf][nf][2], acc[mf][nf][3]);

    TC_GEMM_BODY(A2_SRC, Wp, H, EI, EPI2)
#undef A2_SRC
#undef EPI2
}

// ---------------------------------------------------------------------------
// Launch
// ---------------------------------------------------------------------------
extern "C" void kernel_launch(void* const* d_in, const int* in_sizes, int n_in,
                              void* d_out, int out_size) {
    const float* x         = (const float*)d_in[0];
    const int*   token_ids = (const int*)d_in[1];
    const float* gate_up   = (const float*)d_in[2];
    const float* down      = (const float*)d_in[3];
    float*       out       = (float*)d_out;

    cudaFuncSetAttribute(gemm1_kernel, cudaFuncAttributeMaxDynamicSharedMemorySize, SMEM_BYTES);
    cudaFuncSetAttribute(gemm2_kernel, cudaFuncAttributeMaxDynamicSharedMemorySize, SMEM_BYTES);

    prep_kernel<<<NXB + 1, 256>>>(x, token_ids);

    dim3 grid1(2 * EI / BN, NT / BM, NE);
    gemm1_kernel<<<grid1, 256, SMEM_BYTES>>>(gate_up);
    act_kernel<<<(NT * EI / 4) / 256, 256>>>();
    dim3 grid2(H / BN, NT / BM, NE);
    gemm2_kernel<<<grid2, 256, SMEM_BYTES>>>(down, out);
}